// round 9
// baseline (speedup 1.0000x reference)
#include <cuda_runtime.h>
#include <math.h>
#include <stdint.h>

#define BB  2
#define SSL 2048
#define DD  1024
#define HH  16
#define HDD 64
#define MSZ (BB*SSL)

// Scratch (device globals). tf32 bit patterns.
// g_q : 0.125*Q, dim-interleaved within 8-groups (j -> 2*(j&3)+(j>>2))
// g_kt: softplus(K), dim-interleaved
// g_v : Q+K, natural dim order
__device__ uint32_t g_q [MSZ*DD];
__device__ uint32_t g_kt[MSZ*DD];
__device__ uint32_t g_v [MSZ*DD];

// ---------------------------------------------------------------------------
// helpers
// ---------------------------------------------------------------------------
__device__ __forceinline__ uint32_t f2tf32(float x) {
    uint32_t r;
    asm("cvt.rna.tf32.f32 %0, %1;" : "=r"(r) : "f"(x));
    return r;
}

__device__ __forceinline__ void mma_tf32(float c[4], const uint32_t a[4],
                                         uint32_t b0, uint32_t b1) {
    asm volatile(
        "mma.sync.aligned.m16n8k8.row.col.f32.tf32.tf32.f32 "
        "{%0,%1,%2,%3}, {%4,%5,%6,%7}, {%8,%9}, {%0,%1,%2,%3};"
        : "+f"(c[0]), "+f"(c[1]), "+f"(c[2]), "+f"(c[3])
        : "r"(a[0]), "r"(a[1]), "r"(a[2]), "r"(a[3]), "r"(b0), "r"(b1));
}

__device__ __forceinline__ float softplus_f(float x) {
    return (x > 15.0f) ? x : log1pf(__expf(x));
}

__device__ __forceinline__ void cpa16(void* s, const void* g) {
    uint32_t sa = (uint32_t)__cvta_generic_to_shared(s);
    asm volatile("cp.async.ca.shared.global [%0], [%1], 16;" :: "r"(sa), "l"(g));
}
#define CP_COMMIT() asm volatile("cp.async.commit_group;")
#define CP_WAIT0()  asm volatile("cp.async.wait_group 0;")

// ---------------------------------------------------------------------------
// Fused projection (r6 body): Q and K on the same X tile; epilogue writes
// g_q (0.125 scale, interleaved tf32), g_kt (softplus, interleaved tf32),
// g_v (Q+K, natural tf32). CTA 128m x 64n, k-tile 32, double-buffered smem.
// ---------------------------------------------------------------------------
#define XS_STR 36
#define WS_STR 72
#define XS_BUF (128*XS_STR)
#define WS_BUF (32*WS_STR)
#define PROJ_SMEM ((2*XS_BUF + 4*WS_BUF)*4)

__global__ void __launch_bounds__(256, 2) proj_tc(
    const float* __restrict__ X,
    const float* __restrict__ Wq, const float* __restrict__ bq,
    const float* __restrict__ Wk, const float* __restrict__ bk)
{
    extern __shared__ uint32_t psm[];
    uint32_t* XsB  = psm;
    uint32_t* WqsB = psm + 2*XS_BUF;
    uint32_t* WksB = WqsB + 2*WS_BUF;

    const int m0 = blockIdx.y * 128;
    const int n0 = blockIdx.x * 64;
    const int t    = threadIdx.x;
    const int warp = t >> 5;
    const int lane = t & 31;
    const int lq   = lane & 3;
    const int lr   = lane >> 2;
    const int wm = (warp >> 1) * 32;
    const int wn = (warp & 1) * 32;

    const int xr = t >> 1;
    const int xcb = (t & 1) * 4;
    const int wr = t >> 3;
    const int wcb = t & 7;

    float accq[2][4][4] = {};
    float acck[2][4][4] = {};

    {
        const float* xp = X + (size_t)(m0 + xr) * DD;
        #pragma unroll
        for (int j = 0; j < 4; j++) {
            int c = xcb + j;
            float4 f = *(const float4*)(xp + 4*c);
            *(uint4*)&XsB[xr*XS_STR + 4*c] =
                make_uint4(f2tf32(f.x), f2tf32(f.y), f2tf32(f.z), f2tf32(f.w));
        }
        const float* wqp = Wq + (size_t)wr * DD + n0;
        const float* wkp = Wk + (size_t)wr * DD + n0;
        #pragma unroll
        for (int j = 0; j < 2; j++) {
            int c = wcb + 8*j;
            float4 fq = *(const float4*)(wqp + 4*c);
            *(uint4*)&WqsB[wr*WS_STR + 4*c] =
                make_uint4(f2tf32(fq.x), f2tf32(fq.y), f2tf32(fq.z), f2tf32(fq.w));
            float4 fk = *(const float4*)(wkp + 4*c);
            *(uint4*)&WksB[wr*WS_STR + 4*c] =
                make_uint4(f2tf32(fk.x), f2tf32(fk.y), f2tf32(fk.z), f2tf32(fk.w));
        }
    }
    __syncthreads();

    for (int k0 = 0; k0 < DD; k0 += 32) {
        const int buf = (k0 >> 5) & 1;
        uint32_t* Xs  = XsB  + buf*XS_BUF;
        uint32_t* Wqs = WqsB + buf*WS_BUF;
        uint32_t* Wks = WksB + buf*WS_BUF;
        const bool more = (k0 + 32) < DD;

        float4 xst[4], wqst[2], wkst[2];
        if (more) {
            const float* xp = X + (size_t)(m0 + xr) * DD + k0 + 32;
            #pragma unroll
            for (int j = 0; j < 4; j++)
                xst[j] = *(const float4*)(xp + 4*(xcb + j));
            const float* wqp = Wq + (size_t)(k0 + 32 + wr) * DD + n0;
            const float* wkp = Wk + (size_t)(k0 + 32 + wr) * DD + n0;
            #pragma unroll
            for (int j = 0; j < 2; j++) {
                wqst[j] = *(const float4*)(wqp + 4*(wcb + 8*j));
                wkst[j] = *(const float4*)(wkp + 4*(wcb + 8*j));
            }
        }

        #pragma unroll
        for (int ks = 0; ks < 4; ks++) {
            int kb = ks * 8;
            uint32_t a[2][4];
            #pragma unroll
            for (int mt = 0; mt < 2; mt++) {
                int ar = wm + 16*mt + lr;
                a[mt][0] = Xs[ar*XS_STR + kb + lq];
                a[mt][1] = Xs[(ar+8)*XS_STR + kb + lq];
                a[mt][2] = Xs[ar*XS_STR + kb + lq + 4];
                a[mt][3] = Xs[(ar+8)*XS_STR + kb + lq + 4];
            }
            #pragma unroll
            for (int nt = 0; nt < 4; nt++) {
                int bc = wn + 8*nt + lr;
                uint32_t q0 = Wqs[(kb + lq)*WS_STR + bc];
                uint32_t q1 = Wqs[(kb + 4 + lq)*WS_STR + bc];
                uint32_t k0r = Wks[(kb + lq)*WS_STR + bc];
                uint32_t k1r = Wks[(kb + 4 + lq)*WS_STR + bc];
                #pragma unroll
                for (int mt = 0; mt < 2; mt++) {
                    mma_tf32(accq[mt][nt], a[mt], q0, q1);
                    mma_tf32(acck[mt][nt], a[mt], k0r, k1r);
                }
            }
        }

        if (more) {
            uint32_t* Xn  = XsB  + (buf^1)*XS_BUF;
            uint32_t* Wqn = WqsB + (buf^1)*WS_BUF;
            uint32_t* Wkn = WksB + (buf^1)*WS_BUF;
            #pragma unroll
            for (int j = 0; j < 4; j++) {
                float4 f = xst[j];
                *(uint4*)&Xn[xr*XS_STR + 4*(xcb + j)] =
                    make_uint4(f2tf32(f.x), f2tf32(f.y), f2tf32(f.z), f2tf32(f.w));
            }
            #pragma unroll
            for (int j = 0; j < 2; j++) {
                float4 fq = wqst[j];
                *(uint4*)&Wqn[wr*WS_STR + 4*(wcb + 8*j)] =
                    make_uint4(f2tf32(fq.x), f2tf32(fq.y), f2tf32(fq.z), f2tf32(fq.w));
                float4 fk = wkst[j];
                *(uint4*)&Wkn[wr*WS_STR + 4*(wcb + 8*j)] =
                    make_uint4(f2tf32(fk.x), f2tf32(fk.y), f2tf32(fk.z), f2tf32(fk.w));
            }
        }
        __syncthreads();
    }

    // epilogue: g_q (scaled, interleaved), g_kt (softplus, interleaved),
    // g_v (natural), all tf32 bits
    #pragma unroll
    for (int nt = 0; nt < 4; nt++) {
        int c = n0 + wn + 8*nt + 2*lq;
        float bqx = bq[c], bqy = bq[c+1];
        float bkx = bk[c], bky = bk[c+1];
        int cb = c & ~7, j = c & 7;
        int j0 = 2*(j&3) + (j>>2);
        int j1 = 2*((j+1)&3) + ((j+1)>>2);
        #pragma unroll
        for (int mt = 0; mt < 2; mt++) {
            #pragma unroll
            for (int half = 0; half < 2; half++) {
                int r = m0 + wm + 16*mt + lr + 8*half;
                float qx = accq[mt][nt][2*half+0] + bqx;
                float qy = accq[mt][nt][2*half+1] + bqy;
                float kx = acck[mt][nt][2*half+0] + bkx;
                float ky = acck[mt][nt][2*half+1] + bky;
                size_t off = (size_t)r * DD;
                g_q [off + cb + j0] = f2tf32(0.125f*qx);
                g_q [off + cb + j1] = f2tf32(0.125f*qy);
                g_kt[off + cb + j0] = f2tf32(softplus_f(kx));
                g_kt[off + cb + j1] = f2tf32(softplus_f(ky));
                *(uint2*)&g_v[off + c] = make_uint2(f2tf32(qx+kx), f2tf32(qy+ky));
            }
        }
    }
}

// ---------------------------------------------------------------------------
// Flash attention v5: Q-tile 128, 256 threads (8 warps, warp tile 16x64),
// 2 CTAs/SM (16 warps/SM). Q-fragments persistent in registers (loaded once
// from interleaved global, LDG.64). K/V double-buffered via cp.async.
// Streamed no-max softmax (2 halves, accS = 16 regs). One sync per tile.
// Query-axis mask -> row p=1 (uniform softmax, matches reference).
// ---------------------------------------------------------------------------
#define AK_STR 72
#define AV_STR 72
#define AP_STR 68
#define KBUF (64*AK_STR)
#define VBUF (64*AV_STR)
#define SMEM_ATTN ((2*KBUF + 2*VBUF + 128*AP_STR)*4)

__global__ void __launch_bounds__(256, 2) attn_tc(
    const int* __restrict__ amask, float* __restrict__ out)
{
    extern __shared__ uint32_t smu[];
    uint32_t* KsB = smu;                  // [2][64][AK_STR] interleaved dims
    uint32_t* VsB = KsB + 2*KBUF;         // [2][64][AV_STR] natural dims
    uint32_t* Ps  = VsB + 2*VBUF;         // [128][AP_STR]

    const int qt = blockIdx.x, h = blockIdx.y, b = blockIdx.z;
    const int t    = threadIdx.x;
    const int warp = t >> 5;
    const int lane = t & 31;
    const int lq   = lane & 3;
    const int lr   = lane >> 2;
    const int r0 = warp*16 + lr, r1 = r0 + 8;
    const int krow = t >> 2, kv = t & 3;   // K/V loader: 64 rows x 4 chunks

    {   // K/V tile 0 -> buffer 0 (async)
        size_t base = ((size_t)(b*SSL + krow))*DD + h*HDD;
        #pragma unroll
        for (int j = 0; j < 4; j++) {
            int c = kv + 4*j;
            cpa16(&KsB[krow*AK_STR + 4*c], g_kt + base + 4*c);
            cpa16(&VsB[krow*AV_STR + 4*c], g_v  + base + 4*c);
        }
        CP_COMMIT();
    }

    // Q fragments: persistent across all key tiles. Interleaved global ->
    // LDG.64 gives (k=8ks+lq, k=8ks+lq+4) adjacent.
    uint32_t aq[8][4];
    {
        const uint32_t* q0p = g_q + ((size_t)(b*SSL + qt*128 + r0))*DD + h*HDD;
        const uint32_t* q1p = g_q + ((size_t)(b*SSL + qt*128 + r1))*DD + h*HDD;
        #pragma unroll
        for (int ks = 0; ks < 8; ks++) {
            uint2 u0 = *(const uint2*)(q0p + 8*ks + 2*lq);
            uint2 u1 = *(const uint2*)(q1p + 8*ks + 2*lq);
            aq[ks][0] = u0.x; aq[ks][1] = u1.x;
            aq[ks][2] = u0.y; aq[ks][3] = u1.y;
        }
    }
    const bool mA = (amask[b*SSL + qt*128 + r0] == 0);
    const bool mB = (amask[b*SSL + qt*128 + r1] == 0);

    float tl0 = 0.0f, tl1 = 0.0f;
    float accO[8][4] = {};
    CP_WAIT0();
    __syncthreads();

    for (int it = 0; it < SSL/64; it++) {
        const int buf = it & 1;
        uint32_t* Ks = KsB + buf*KBUF;
        uint32_t* Vs = VsB + buf*VBUF;

        if (it + 1 < SSL/64) {   // async prefetch next tile into buf^1
            uint32_t* Kn = KsB + (buf^1)*KBUF;
            uint32_t* Vn = VsB + (buf^1)*VBUF;
            size_t base = ((size_t)(b*SSL + (it+1)*64 + krow))*DD + h*HDD;
            #pragma unroll
            for (int j = 0; j < 4; j++) {
                int c = kv + 4*j;
                cpa16(&Kn[krow*AK_STR + 4*c], g_kt + base + 4*c);
                cpa16(&Vn[krow*AV_STR + 4*c], g_v  + base + 4*c);
            }
            CP_COMMIT();
        }

        // ---- S + softmax, streamed in 2 halves of 4 key-blocks ----
        #pragma unroll
        for (int half = 0; half < 2; half++) {
            float accS[4][4] = {};
            #pragma unroll
            for (int ks = 0; ks < 8; ks++) {
                int kb = ks * 8;
                #pragma unroll
                for (int j = 0; j < 4; j++) {
                    int key0 = 8*(4*half + j) + lr;
                    uint2 bb = *(const uint2*)&Ks[key0*AK_STR + kb + 2*lq];
                    mma_tf32(accS[j], aq[ks], bb.x, bb.y);
                }
            }
            #pragma unroll
            for (int j = 0; j < 4; j++) {
                int nt = 4*half + j;
                float p00 = mA ? 1.0f : __expf(accS[j][0]);
                float p01 = mA ? 1.0f : __expf(accS[j][1]);
                float p10 = mB ? 1.0f : __expf(accS[j][2]);
                float p11 = mB ? 1.0f : __expf(accS[j][3]);
                tl0 += p00 + p01;
                tl1 += p10 + p11;
                *(uint2*)&Ps[r0*AP_STR + 8*nt + 2*lq] =
                    make_uint2(__float_as_uint(p00), __float_as_uint(p01));
                *(uint2*)&Ps[r1*AP_STR + 8*nt + 2*lq] =
                    make_uint2(__float_as_uint(p10), __float_as_uint(p11));
            }
        }
        __syncwarp();   // Ps rows owned and read by this warp only

        // ---- O += P @ V ----
        #pragma unroll
        for (int ks = 0; ks < 8; ks++) {
            int kb = ks * 8;
            uint32_t a[4];
            a[0] = Ps[r0*AP_STR + kb + lq];
            a[1] = Ps[r1*AP_STR + kb + lq];
            a[2] = Ps[r0*AP_STR + kb + 4 + lq];
            a[3] = Ps[r1*AP_STR + kb + 4 + lq];
            #pragma unroll
            for (int nt = 0; nt < 8; nt++) {
                int bc = 8*nt + lr;
                uint32_t b0 = Vs[(kb + lq)*AV_STR + bc];
                uint32_t b1 = Vs[(kb + 4 + lq)*AV_STR + bc];
                mma_tf32(accO[nt], a, b0, b1);
            }
        }
        CP_WAIT0();
        __syncthreads();
    }

    // ---- epilogue: reduce l across quad, write O / l ----
    tl0 += __shfl_xor_sync(0xffffffffu, tl0, 1);
    tl0 += __shfl_xor_sync(0xffffffffu, tl0, 2);
    tl1 += __shfl_xor_sync(0xffffffffu, tl1, 1);
    tl1 += __shfl_xor_sync(0xffffffffu, tl1, 2);
    float li0 = 1.0f / tl0, li1 = 1.0f / tl1;
    size_t row0 = (size_t)(b*SSL + qt*128 + r0) * DD + h*HDD;
    size_t row1 = (size_t)(b*SSL + qt*128 + r1) * DD + h*HDD;
    #pragma unroll
    for (int nt = 0; nt < 8; nt++) {
        int col = 8*nt + 2*lq;
        *(float2*)(out + row0 + col) = make_float2(accO[nt][0]*li0, accO[nt][1]*li0);
        *(float2*)(out + row1 + col) = make_float2(accO[nt][2]*li1, accO[nt][3]*li1);
    }
}

// ---------------------------------------------------------------------------
extern "C" void kernel_launch(void* const* d_in, const int* in_sizes, int n_in,
                              void* d_out, int out_size)
{
    const float* X     = (const float*)d_in[0];
    const int*   amask = (const int*)  d_in[1];
    const float* Wq    = (const float*)d_in[2];
    const float* bq    = (const float*)d_in[3];
    const float* Wk    = (const float*)d_in[4];
    const float* bk    = (const float*)d_in[5];
    float*       out   = (float*)d_out;

    cudaFuncSetAttribute(proj_tc,
                         cudaFuncAttributeMaxDynamicSharedMemorySize, PROJ_SMEM);
    cudaFuncSetAttribute(attn_tc,
                         cudaFuncAttributeMaxDynamicSharedMemorySize, SMEM_ATTN);

    proj_tc<<<dim3(DD/64, MSZ/128), 256, PROJ_SMEM>>>(X, Wq, bq, Wk, bk);
    attn_tc<<<dim3(SSL/128, HH, BB), 256, SMEM_ATTN>>>(amask, out);
}

// round 10
// speedup vs baseline: 1.4564x; 1.4564x over previous
#include <cuda_runtime.h>
#include <math.h>
#include <stdint.h>

#define BB  2
#define SSL 2048
#define DD  1024
#define HH  16
#define HDD 64
#define MSZ (BB*SSL)

// Scratch (allocation-free rule: device globals)
__device__ float g_q[MSZ*DD];
__device__ float g_kt[MSZ*DD];   // softplus(K)
__device__ float g_v[MSZ*DD];    // Q + K

// ---------------------------------------------------------------------------
// tf32 helpers
// ---------------------------------------------------------------------------
__device__ __forceinline__ uint32_t f2tf32(float x) {
    uint32_t r;
    asm("cvt.rna.tf32.f32 %0, %1;" : "=r"(r) : "f"(x));
    return r;
}

__device__ __forceinline__ void mma_tf32(float c[4], const uint32_t a[4],
                                         uint32_t b0, uint32_t b1) {
    asm volatile(
        "mma.sync.aligned.m16n8k8.row.col.f32.tf32.tf32.f32 "
        "{%0,%1,%2,%3}, {%4,%5,%6,%7}, {%8,%9}, {%0,%1,%2,%3};"
        : "+f"(c[0]), "+f"(c[1]), "+f"(c[2]), "+f"(c[3])
        : "r"(a[0]), "r"(a[1]), "r"(a[2]), "r"(a[3]), "r"(b0), "r"(b1));
}

__device__ __forceinline__ float softplus_f(float x) {
    return (x > 15.0f) ? x : log1pf(__expf(x));
}

// ---------------------------------------------------------------------------
// Fused projection (r6, known-good): Q and K on the same X tile,
// epilogue writes g_q, g_kt=softplus(K), g_v=Q+K.
// ---------------------------------------------------------------------------
#define XS_STR 36
#define WS_STR 72
#define XS_BUF (128*XS_STR)
#define WS_BUF (32*WS_STR)
#define PROJ_SMEM ((2*XS_BUF + 4*WS_BUF)*4)

__global__ void __launch_bounds__(256, 2) proj_tc(
    const float* __restrict__ X,
    const float* __restrict__ Wq, const float* __restrict__ bq,
    const float* __restrict__ Wk, const float* __restrict__ bk)
{
    extern __shared__ uint32_t psm[];
    uint32_t* XsB  = psm;
    uint32_t* WqsB = psm + 2*XS_BUF;
    uint32_t* WksB = WqsB + 2*WS_BUF;

    const int m0 = blockIdx.y * 128;
    const int n0 = blockIdx.x * 64;
    const int t    = threadIdx.x;
    const int warp = t >> 5;
    const int lane = t & 31;
    const int lq   = lane & 3;
    const int lr   = lane >> 2;
    const int wm = (warp >> 1) * 32;
    const int wn = (warp & 1) * 32;

    const int xr = t >> 1;
    const int xcb = (t & 1) * 4;
    const int wr = t >> 3;
    const int wcb = t & 7;

    float accq[2][4][4] = {};
    float acck[2][4][4] = {};

    {
        const float* xp = X + (size_t)(m0 + xr) * DD;
        #pragma unroll
        for (int j = 0; j < 4; j++) {
            int c = xcb + j;
            float4 f = *(const float4*)(xp + 4*c);
            *(uint4*)&XsB[xr*XS_STR + 4*c] =
                make_uint4(f2tf32(f.x), f2tf32(f.y), f2tf32(f.z), f2tf32(f.w));
        }
        const float* wqp = Wq + (size_t)wr * DD + n0;
        const float* wkp = Wk + (size_t)wr * DD + n0;
        #pragma unroll
        for (int j = 0; j < 2; j++) {
            int c = wcb + 8*j;
            float4 fq = *(const float4*)(wqp + 4*c);
            *(uint4*)&WqsB[wr*WS_STR + 4*c] =
                make_uint4(f2tf32(fq.x), f2tf32(fq.y), f2tf32(fq.z), f2tf32(fq.w));
            float4 fk = *(const float4*)(wkp + 4*c);
            *(uint4*)&WksB[wr*WS_STR + 4*c] =
                make_uint4(f2tf32(fk.x), f2tf32(fk.y), f2tf32(fk.z), f2tf32(fk.w));
        }
    }
    __syncthreads();

    for (int k0 = 0; k0 < DD; k0 += 32) {
        const int buf = (k0 >> 5) & 1;
        uint32_t* Xs  = XsB  + buf*XS_BUF;
        uint32_t* Wqs = WqsB + buf*WS_BUF;
        uint32_t* Wks = WksB + buf*WS_BUF;
        const bool more = (k0 + 32) < DD;

        float4 xst[4], wqst[2], wkst[2];
        if (more) {
            const float* xp = X + (size_t)(m0 + xr) * DD + k0 + 32;
            #pragma unroll
            for (int j = 0; j < 4; j++)
                xst[j] = *(const float4*)(xp + 4*(xcb + j));
            const float* wqp = Wq + (size_t)(k0 + 32 + wr) * DD + n0;
            const float* wkp = Wk + (size_t)(k0 + 32 + wr) * DD + n0;
            #pragma unroll
            for (int j = 0; j < 2; j++) {
                wqst[j] = *(const float4*)(wqp + 4*(wcb + 8*j));
                wkst[j] = *(const float4*)(wkp + 4*(wcb + 8*j));
            }
        }

        #pragma unroll
        for (int ks = 0; ks < 4; ks++) {
            int kb = ks * 8;
            uint32_t a[2][4];
            #pragma unroll
            for (int mt = 0; mt < 2; mt++) {
                int ar = wm + 16*mt + lr;
                a[mt][0] = Xs[ar*XS_STR + kb + lq];
                a[mt][1] = Xs[(ar+8)*XS_STR + kb + lq];
                a[mt][2] = Xs[ar*XS_STR + kb + lq + 4];
                a[mt][3] = Xs[(ar+8)*XS_STR + kb + lq + 4];
            }
            #pragma unroll
            for (int nt = 0; nt < 4; nt++) {
                int bc = wn + 8*nt + lr;
                uint32_t q0 = Wqs[(kb + lq)*WS_STR + bc];
                uint32_t q1 = Wqs[(kb + 4 + lq)*WS_STR + bc];
                uint32_t k0r = Wks[(kb + lq)*WS_STR + bc];
                uint32_t k1r = Wks[(kb + 4 + lq)*WS_STR + bc];
                #pragma unroll
                for (int mt = 0; mt < 2; mt++) {
                    mma_tf32(accq[mt][nt], a[mt], q0, q1);
                    mma_tf32(acck[mt][nt], a[mt], k0r, k1r);
                }
            }
        }

        if (more) {
            uint32_t* Xn  = XsB  + (buf^1)*XS_BUF;
            uint32_t* Wqn = WqsB + (buf^1)*WS_BUF;
            uint32_t* Wkn = WksB + (buf^1)*WS_BUF;
            #pragma unroll
            for (int j = 0; j < 4; j++) {
                float4 f = xst[j];
                *(uint4*)&Xn[xr*XS_STR + 4*(xcb + j)] =
                    make_uint4(f2tf32(f.x), f2tf32(f.y), f2tf32(f.z), f2tf32(f.w));
            }
            #pragma unroll
            for (int j = 0; j < 2; j++) {
                float4 fq = wqst[j];
                *(uint4*)&Wqn[wr*WS_STR + 4*(wcb + 8*j)] =
                    make_uint4(f2tf32(fq.x), f2tf32(fq.y), f2tf32(fq.z), f2tf32(fq.w));
                float4 fk = wkst[j];
                *(uint4*)&Wkn[wr*WS_STR + 4*(wcb + 8*j)] =
                    make_uint4(f2tf32(fk.x), f2tf32(fk.y), f2tf32(fk.z), f2tf32(fk.w));
            }
        }
        __syncthreads();
    }

    #pragma unroll
    for (int nt = 0; nt < 4; nt++) {
        int c = n0 + wn + 8*nt + 2*lq;
        float bqx = bq[c], bqy = bq[c+1];
        float bkx = bk[c], bky = bk[c+1];
        #pragma unroll
        for (int mt = 0; mt < 2; mt++) {
            #pragma unroll
            for (int half = 0; half < 2; half++) {
                int r = m0 + wm + 16*mt + lr + 8*half;
                float qx = accq[mt][nt][2*half+0] + bqx;
                float qy = accq[mt][nt][2*half+1] + bqy;
                float kx = acck[mt][nt][2*half+0] + bkx;
                float ky = acck[mt][nt][2*half+1] + bky;
                size_t off = (size_t)r * DD + c;
                *(float2*)(g_q  + off) = make_float2(qx, qy);
                *(float2*)(g_kt + off) = make_float2(softplus_f(kx), softplus_f(ky));
                *(float2*)(g_v  + off) = make_float2(qx + kx, qy + ky);
            }
        }
    }
}

// ---------------------------------------------------------------------------
// Flash attention (r6 structure + no-max softmax): Q-tile 256, 256 threads
// (8 warps, warp tile 32x64), double-buffered K/V smem with LDG-early /
// STS-after-softmax prefetch, ONE __syncthreads per key tile.
// Softmax without running max: p = exp(s) (scores bounded), masked query
// rows -> p = 1 (exactly the reference's uniform softmax). l reduced in
// the epilogue. P stored as raw fp32 bits (HW truncates to tf32).
// ---------------------------------------------------------------------------
#define AQ_STR 68
#define AK_STR 68
#define AV_STR 72
#define AP_STR 68
#define KBUF (64*AK_STR)
#define VBUF (64*AV_STR)
#define SMEM_ATTN ((256*AQ_STR + 2*KBUF + 2*VBUF + 256*AP_STR)*4)

__global__ void __launch_bounds__(256, 1) attn_tc(
    const int* __restrict__ amask, float* __restrict__ out)
{
    extern __shared__ uint32_t smu[];
    uint32_t* Qs  = smu;                    // [256][AQ_STR]
    uint32_t* KsB = Qs  + 256*AQ_STR;       // [2][64][AK_STR]
    uint32_t* VsB = KsB + 2*KBUF;           // [2][64][AV_STR]
    uint32_t* Ps  = VsB + 2*VBUF;           // [256][AP_STR]

    const int qt = blockIdx.x, h = blockIdx.y, b = blockIdx.z;
    const int t    = threadIdx.x;
    const int warp = t >> 5;
    const int lane = t & 31;
    const int lq   = lane & 3;
    const int lr   = lane >> 2;
    const int wm   = warp * 32;             // warp's 32 query rows
    const int krow = t >> 2, kv = t & 3;    // K/V loader: 64 rows x 4 chunks

    {   // Q tile: 256 rows, 1 row/thread, tf32 with 1/8 folded
        const float* qp = g_q + ((size_t)(b*SSL + qt*256 + t))*DD + h*HDD;
        #pragma unroll
        for (int c = 0; c < 16; c++) {
            float4 f = *(const float4*)(qp + 4*c);
            *(uint4*)&Qs[t*AQ_STR + 4*c] =
                make_uint4(f2tf32(f.x*0.125f), f2tf32(f.y*0.125f),
                           f2tf32(f.z*0.125f), f2tf32(f.w*0.125f));
        }
    }
    {   // K/V tile 0 -> buffer 0
        size_t base = ((size_t)(b*SSL + krow))*DD + h*HDD;
        #pragma unroll
        for (int j = 0; j < 4; j++) {
            int c = kv + 4*j;
            float4 kf = *(const float4*)(g_kt + base + 4*c);
            *(uint4*)&KsB[krow*AK_STR + 4*c] =
                make_uint4(f2tf32(kf.x), f2tf32(kf.y), f2tf32(kf.z), f2tf32(kf.w));
            float4 vf = *(const float4*)(g_v + base + 4*c);
            *(uint4*)&VsB[krow*AV_STR + 4*c] =
                make_uint4(f2tf32(vf.x), f2tf32(vf.y), f2tf32(vf.z), f2tf32(vf.w));
        }
    }
    // mask flags for this thread's 4 rows
    bool mflag[2][2];
    #pragma unroll
    for (int mt = 0; mt < 2; mt++) {
        mflag[mt][0] = (amask[b*SSL + qt*256 + wm + 16*mt + lr] == 0);
        mflag[mt][1] = (amask[b*SSL + qt*256 + wm + 16*mt + 8 + lr] == 0);
    }

    float tl[2][2] = {{0.0f,0.0f},{0.0f,0.0f}};   // partial l sums
    float accO[2][8][4] = {};
    __syncthreads();

    for (int it = 0; it < SSL/64; it++) {
        const int buf = it & 1;
        uint32_t* Ks = KsB + buf*KBUF;
        uint32_t* Vs = VsB + buf*VBUF;
        const bool more = (it + 1) < SSL/64;

        // prefetch next K/V tile into registers (consumed after softmax)
        float4 pk[4], pv[4];
        if (more) {
            size_t base = ((size_t)(b*SSL + (it+1)*64 + krow))*DD + h*HDD;
            #pragma unroll
            for (int j = 0; j < 4; j++) {
                int c = kv + 4*j;
                pk[j] = *(const float4*)(g_kt + base + 4*c);
                pv[j] = *(const float4*)(g_v  + base + 4*c);
            }
        }

        // ---- S = (Q/8) @ K^T : warp computes 32x64 ----
        float accS[2][8][4] = {};
        #pragma unroll
        for (int ks = 0; ks < 8; ks++) {
            int kb = ks * 8;
            uint32_t a[2][4];
            #pragma unroll
            for (int mt = 0; mt < 2; mt++) {
                int ar = wm + 16*mt + lr;
                a[mt][0] = Qs[ar*AQ_STR + kb + lq];
                a[mt][1] = Qs[(ar+8)*AQ_STR + kb + lq];
                a[mt][2] = Qs[ar*AQ_STR + kb + 4 + lq];
                a[mt][3] = Qs[(ar+8)*AQ_STR + kb + 4 + lq];
            }
            #pragma unroll
            for (int nt = 0; nt < 8; nt++) {
                int key0 = 8*nt + lr;
                uint32_t b0 = Ks[key0*AK_STR + kb + lq];
                uint32_t b1 = Ks[key0*AK_STR + kb + 4 + lq];
                mma_tf32(accS[0][nt], a[0], b0, b1);
                mma_tf32(accS[1][nt], a[1], b0, b1);
            }
        }

        // ---- no-max softmax: p = exp(s); masked rows p = 1 ----
        #pragma unroll
        for (int mt = 0; mt < 2; mt++) {
            const bool mA = mflag[mt][0], mB = mflag[mt][1];
            int ra = wm + 16*mt + lr, rb = ra + 8;
            float s0 = 0.0f, s1 = 0.0f;
            #pragma unroll
            for (int nt = 0; nt < 8; nt++) {
                float p00 = mA ? 1.0f : __expf(accS[mt][nt][0]);
                float p01 = mA ? 1.0f : __expf(accS[mt][nt][1]);
                float p10 = mB ? 1.0f : __expf(accS[mt][nt][2]);
                float p11 = mB ? 1.0f : __expf(accS[mt][nt][3]);
                s0 += p00 + p01;
                s1 += p10 + p11;
                *(uint2*)&Ps[ra*AP_STR + 8*nt + 2*lq] =
                    make_uint2(__float_as_uint(p00), __float_as_uint(p01));
                *(uint2*)&Ps[rb*AP_STR + 8*nt + 2*lq] =
                    make_uint2(__float_as_uint(p10), __float_as_uint(p11));
            }
            tl[mt][0] += s0;
            tl[mt][1] += s1;
        }
        __syncwarp();   // Ps rows owned and read by this warp only

        // ---- stash prefetched K/V into the other buffer ----
        if (more) {
            uint32_t* Kn = KsB + (buf^1)*KBUF;
            uint32_t* Vn = VsB + (buf^1)*VBUF;
            #pragma unroll
            for (int j = 0; j < 4; j++) {
                int c = kv + 4*j;
                *(uint4*)&Kn[krow*AK_STR + 4*c] =
                    make_uint4(f2tf32(pk[j].x), f2tf32(pk[j].y),
                               f2tf32(pk[j].z), f2tf32(pk[j].w));
                *(uint4*)&Vn[krow*AV_STR + 4*c] =
                    make_uint4(f2tf32(pv[j].x), f2tf32(pv[j].y),
                               f2tf32(pv[j].z), f2tf32(pv[j].w));
            }
        }

        // ---- O += P @ V ----
        #pragma unroll
        for (int ks = 0; ks < 8; ks++) {
            int kb = ks * 8;
            uint32_t a[2][4];
            #pragma unroll
            for (int mt = 0; mt < 2; mt++) {
                int ar = wm + 16*mt + lr;
                a[mt][0] = Ps[ar*AP_STR + kb + lq];
                a[mt][1] = Ps[(ar+8)*AP_STR + kb + lq];
                a[mt][2] = Ps[ar*AP_STR + kb + 4 + lq];
                a[mt][3] = Ps[(ar+8)*AP_STR + kb + 4 + lq];
            }
            #pragma unroll
            for (int nt = 0; nt < 8; nt++) {
                int bc = 8*nt + lr;
                uint32_t b0 = Vs[(kb + lq)*AV_STR + bc];
                uint32_t b1 = Vs[(kb + 4 + lq)*AV_STR + bc];
                mma_tf32(accO[0][nt], a[0], b0, b1);
                mma_tf32(accO[1][nt], a[1], b0, b1);
            }
        }
        __syncthreads();   // tile done: buf consumed by all, buf^1 fully written
    }

    // ---- epilogue: reduce l across quad, write O / l ----
    #pragma unroll
    for (int mt = 0; mt < 2; mt++) {
        #pragma unroll
        for (int half = 0; half < 2; half++) {
            float v = tl[mt][half];
            v += __shfl_xor_sync(0xffffffffu, v, 1);
            v += __shfl_xor_sync(0xffffffffu, v, 2);
            tl[mt][half] = v;
        }
    }
    #pragma unroll
    for (int mt = 0; mt < 2; mt++) {
        int ra = wm + 16*mt + lr, rb = ra + 8;
        float li0 = 1.0f / tl[mt][0], li1 = 1.0f / tl[mt][1];
        size_t row0 = (size_t)(b*SSL + qt*256 + ra) * DD + h*HDD;
        size_t row1 = (size_t)(b*SSL + qt*256 + rb) * DD + h*HDD;
        #pragma unroll
        for (int nt = 0; nt < 8; nt++) {
            int col = 8*nt + 2*lq;
            *(float2*)(out + row0 + col) =
                make_float2(accO[mt][nt][0]*li0, accO[mt][nt][1]*li0);
            *(float2*)(out + row1 + col) =
                make_float2(accO[mt][nt][2]*li1, accO[mt][nt][3]*li1);
        }
    }
}

// ---------------------------------------------------------------------------
extern "C" void kernel_launch(void* const* d_in, const int* in_sizes, int n_in,
                              void* d_out, int out_size)
{
    const float* X     = (const float*)d_in[0];
    const int*   amask = (const int*)  d_in[1];
    const float* Wq    = (const float*)d_in[2];
    const float* bq    = (const float*)d_in[3];
    const float* Wk    = (const float*)d_in[4];
    const float* bk    = (const float*)d_in[5];
    float*       out   = (float*)d_out;

    cudaFuncSetAttribute(proj_tc,
                         cudaFuncAttributeMaxDynamicSharedMemorySize, PROJ_SMEM);
    cudaFuncSetAttribute(attn_tc,
                         cudaFuncAttributeMaxDynamicSharedMemorySize, SMEM_ATTN);

    proj_tc<<<dim3(DD/64, MSZ/128), 256, PROJ_SMEM>>>(X, Wq, bq, Wk, bk);
    attn_tc<<<dim3(SSL/256, HH, BB), 256, SMEM_ATTN>>>(amask, out);
}

// round 11
// speedup vs baseline: 1.5810x; 1.0856x over previous
#include <cuda_runtime.h>
#include <math.h>
#include <stdint.h>

#define BB  2
#define SSL 2048
#define DD  1024
#define HH  16
#define HDD 64
#define MSZ (BB*SSL)

// Scratch (allocation-free rule: device globals). All tf32 bit patterns:
// g_q  = tf32(0.125 * Q)     (scale folded at proj epilogue)
// g_kt = tf32(softplus(K))
// g_v  = tf32(Q + K)
__device__ uint32_t g_q [MSZ*DD];
__device__ uint32_t g_kt[MSZ*DD];
__device__ uint32_t g_v [MSZ*DD];

// ---------------------------------------------------------------------------
// helpers
// ---------------------------------------------------------------------------
__device__ __forceinline__ uint32_t f2tf32(float x) {
    uint32_t r;
    asm("cvt.rna.tf32.f32 %0, %1;" : "=r"(r) : "f"(x));
    return r;
}

__device__ __forceinline__ void mma_tf32(float c[4], const uint32_t a[4],
                                         uint32_t b0, uint32_t b1) {
    asm volatile(
        "mma.sync.aligned.m16n8k8.row.col.f32.tf32.tf32.f32 "
        "{%0,%1,%2,%3}, {%4,%5,%6,%7}, {%8,%9}, {%0,%1,%2,%3};"
        : "+f"(c[0]), "+f"(c[1]), "+f"(c[2]), "+f"(c[3])
        : "r"(a[0]), "r"(a[1]), "r"(a[2]), "r"(a[3]), "r"(b0), "r"(b1));
}

__device__ __forceinline__ float softplus_f(float x) {
    return (x > 15.0f) ? x : log1pf(__expf(x));
}

__device__ __forceinline__ void cpa16(void* s, const void* g) {
    uint32_t sa = (uint32_t)__cvta_generic_to_shared(s);
    asm volatile("cp.async.ca.shared.global [%0], [%1], 16;" :: "r"(sa), "l"(g));
}
#define CP_COMMIT() asm volatile("cp.async.commit_group;")
#define CP_WAIT0()  asm volatile("cp.async.wait_group 0;")

// ---------------------------------------------------------------------------
// Fused projection (r6 body, known-good): Q and K on the same X tile.
// Epilogue writes tf32 bits: g_q = tf32(0.125*Q), g_kt = tf32(softplus(K)),
// g_v = tf32(Q+K). CTA 128m x 64n, k-tile 32, double-buffered smem.
// ---------------------------------------------------------------------------
#define XS_STR 36
#define WS_STR 72
#define XS_BUF (128*XS_STR)
#define WS_BUF (32*WS_STR)
#define PROJ_SMEM ((2*XS_BUF + 4*WS_BUF)*4)

__global__ void __launch_bounds__(256, 2) proj_tc(
    const float* __restrict__ X,
    const float* __restrict__ Wq, const float* __restrict__ bq,
    const float* __restrict__ Wk, const float* __restrict__ bk)
{
    extern __shared__ uint32_t psm[];
    uint32_t* XsB  = psm;
    uint32_t* WqsB = psm + 2*XS_BUF;
    uint32_t* WksB = WqsB + 2*WS_BUF;

    const int m0 = blockIdx.y * 128;
    const int n0 = blockIdx.x * 64;
    const int t    = threadIdx.x;
    const int warp = t >> 5;
    const int lane = t & 31;
    const int lq   = lane & 3;
    const int lr   = lane >> 2;
    const int wm = (warp >> 1) * 32;
    const int wn = (warp & 1) * 32;

    const int xr = t >> 1;
    const int xcb = (t & 1) * 4;
    const int wr = t >> 3;
    const int wcb = t & 7;

    float accq[2][4][4] = {};
    float acck[2][4][4] = {};

    {
        const float* xp = X + (size_t)(m0 + xr) * DD;
        #pragma unroll
        for (int j = 0; j < 4; j++) {
            int c = xcb + j;
            float4 f = *(const float4*)(xp + 4*c);
            *(uint4*)&XsB[xr*XS_STR + 4*c] =
                make_uint4(f2tf32(f.x), f2tf32(f.y), f2tf32(f.z), f2tf32(f.w));
        }
        const float* wqp = Wq + (size_t)wr * DD + n0;
        const float* wkp = Wk + (size_t)wr * DD + n0;
        #pragma unroll
        for (int j = 0; j < 2; j++) {
            int c = wcb + 8*j;
            float4 fq = *(const float4*)(wqp + 4*c);
            *(uint4*)&WqsB[wr*WS_STR + 4*c] =
                make_uint4(f2tf32(fq.x), f2tf32(fq.y), f2tf32(fq.z), f2tf32(fq.w));
            float4 fk = *(const float4*)(wkp + 4*c);
            *(uint4*)&WksB[wr*WS_STR + 4*c] =
                make_uint4(f2tf32(fk.x), f2tf32(fk.y), f2tf32(fk.z), f2tf32(fk.w));
        }
    }
    __syncthreads();

    for (int k0 = 0; k0 < DD; k0 += 32) {
        const int buf = (k0 >> 5) & 1;
        uint32_t* Xs  = XsB  + buf*XS_BUF;
        uint32_t* Wqs = WqsB + buf*WS_BUF;
        uint32_t* Wks = WksB + buf*WS_BUF;
        const bool more = (k0 + 32) < DD;

        float4 xst[4], wqst[2], wkst[2];
        if (more) {
            const float* xp = X + (size_t)(m0 + xr) * DD + k0 + 32;
            #pragma unroll
            for (int j = 0; j < 4; j++)
                xst[j] = *(const float4*)(xp + 4*(xcb + j));
            const float* wqp = Wq + (size_t)(k0 + 32 + wr) * DD + n0;
            const float* wkp = Wk + (size_t)(k0 + 32 + wr) * DD + n0;
            #pragma unroll
            for (int j = 0; j < 2; j++) {
                wqst[j] = *(const float4*)(wqp + 4*(wcb + 8*j));
                wkst[j] = *(const float4*)(wkp + 4*(wcb + 8*j));
            }
        }

        #pragma unroll
        for (int ks = 0; ks < 4; ks++) {
            int kb = ks * 8;
            uint32_t a[2][4];
            #pragma unroll
            for (int mt = 0; mt < 2; mt++) {
                int ar = wm + 16*mt + lr;
                a[mt][0] = Xs[ar*XS_STR + kb + lq];
                a[mt][1] = Xs[(ar+8)*XS_STR + kb + lq];
                a[mt][2] = Xs[ar*XS_STR + kb + lq + 4];
                a[mt][3] = Xs[(ar+8)*XS_STR + kb + lq + 4];
            }
            #pragma unroll
            for (int nt = 0; nt < 4; nt++) {
                int bc = wn + 8*nt + lr;
                uint32_t q0 = Wqs[(kb + lq)*WS_STR + bc];
                uint32_t q1 = Wqs[(kb + 4 + lq)*WS_STR + bc];
                uint32_t k0r = Wks[(kb + lq)*WS_STR + bc];
                uint32_t k1r = Wks[(kb + 4 + lq)*WS_STR + bc];
                #pragma unroll
                for (int mt = 0; mt < 2; mt++) {
                    mma_tf32(accq[mt][nt], a[mt], q0, q1);
                    mma_tf32(acck[mt][nt], a[mt], k0r, k1r);
                }
            }
        }

        if (more) {
            uint32_t* Xn  = XsB  + (buf^1)*XS_BUF;
            uint32_t* Wqn = WqsB + (buf^1)*WS_BUF;
            uint32_t* Wkn = WksB + (buf^1)*WS_BUF;
            #pragma unroll
            for (int j = 0; j < 4; j++) {
                float4 f = xst[j];
                *(uint4*)&Xn[xr*XS_STR + 4*(xcb + j)] =
                    make_uint4(f2tf32(f.x), f2tf32(f.y), f2tf32(f.z), f2tf32(f.w));
            }
            #pragma unroll
            for (int j = 0; j < 2; j++) {
                float4 fq = wqst[j];
                *(uint4*)&Wqn[wr*WS_STR + 4*(wcb + 8*j)] =
                    make_uint4(f2tf32(fq.x), f2tf32(fq.y), f2tf32(fq.z), f2tf32(fq.w));
                float4 fk = wkst[j];
                *(uint4*)&Wkn[wr*WS_STR + 4*(wcb + 8*j)] =
                    make_uint4(f2tf32(fk.x), f2tf32(fk.y), f2tf32(fk.z), f2tf32(fk.w));
            }
        }
        __syncthreads();
    }

    // epilogue: tf32 bits, natural layout
    #pragma unroll
    for (int nt = 0; nt < 4; nt++) {
        int c = n0 + wn + 8*nt + 2*lq;
        float bqx = bq[c], bqy = bq[c+1];
        float bkx = bk[c], bky = bk[c+1];
        #pragma unroll
        for (int mt = 0; mt < 2; mt++) {
            #pragma unroll
            for (int half = 0; half < 2; half++) {
                int r = m0 + wm + 16*mt + lr + 8*half;
                float qx = accq[mt][nt][2*half+0] + bqx;
                float qy = accq[mt][nt][2*half+1] + bqy;
                float kx = acck[mt][nt][2*half+0] + bkx;
                float ky = acck[mt][nt][2*half+1] + bky;
                size_t off = (size_t)r * DD + c;
                *(uint2*)&g_q [off] = make_uint2(f2tf32(0.125f*qx), f2tf32(0.125f*qy));
                *(uint2*)&g_kt[off] = make_uint2(f2tf32(softplus_f(kx)),
                                                 f2tf32(softplus_f(ky)));
                *(uint2*)&g_v [off] = make_uint2(f2tf32(qx+kx), f2tf32(qy+ky));
            }
        }
    }
}

// ---------------------------------------------------------------------------
// Flash attention v6: Q-tile 128, 256 threads (8 warps, warp tile 16x64),
// 2 CTAs/SM (16 warps/SM). P STAYS IN REGISTERS: the S-MMA C-layout feeds
// the PV-MMA A-operand directly because V rows are permuted within each
// 8-key group (i -> i/2 + 4*(i&1)) at load time (key-sum is permutation-
// invariant). No Ps buffer, no P smem traffic. K/V double-buffered cp.async
// (wait at tile top, covered by a full tile of MMAs). No-max softmax
// (p = exp(s); masked query rows p = 1 -> reference's uniform softmax).
// All global operands are pre-converted tf32 bits -> loads are pure cp.async.
// ---------------------------------------------------------------------------
#define AQ_STR 68
#define AK_STR 68
#define AV_STR 72
#define KBUF (64*AK_STR)
#define VBUF (64*AV_STR)
#define SMEM_ATTN ((128*AQ_STR + 2*KBUF + 2*VBUF)*4)

__global__ void __launch_bounds__(256, 2) attn_tc(
    const int* __restrict__ amask, float* __restrict__ out)
{
    extern __shared__ uint32_t smu[];
    uint32_t* Qs  = smu;                  // [128][AQ_STR]
    uint32_t* KsB = Qs + 128*AQ_STR;      // [2][64][AK_STR]
    uint32_t* VsB = KsB + 2*KBUF;         // [2][64][AV_STR], rows permuted

    const int qt = blockIdx.x, h = blockIdx.y, b = blockIdx.z;
    const int t    = threadIdx.x;
    const int warp = t >> 5;
    const int lane = t & 31;
    const int lq   = lane & 3;
    const int lr   = lane >> 2;
    const int r0 = warp*16 + lr, r1 = r0 + 8;
    const int qrow = t >> 1, qv = t & 1;   // Q loader: 128 rows x 2 threads
    const int krow = t >> 2, kv = t & 3;   // K/V loader: 64 rows x 4 chunks
    // permuted V row: within 8-group, key i -> row i/2 + 4*(i&1)
    const int vprow = (krow & ~7) + ((krow & 7) >> 1) + ((krow & 1) << 2);

    {   // Q tile + K/V tile 0, all async
        const uint32_t* qg = g_q + ((size_t)(b*SSL + qt*128 + qrow))*DD + h*HDD;
        #pragma unroll
        for (int j = 0; j < 8; j++) {
            int c = 8*qv + j;
            cpa16(&Qs[qrow*AQ_STR + 4*c], qg + 4*c);
        }
        size_t base = ((size_t)(b*SSL + krow))*DD + h*HDD;
        #pragma unroll
        for (int j = 0; j < 4; j++) {
            int c = kv + 4*j;
            cpa16(&KsB[krow*AK_STR + 4*c], g_kt + base + 4*c);
            cpa16(&VsB[vprow*AV_STR + 4*c], g_v + base + 4*c);
        }
        CP_COMMIT();
    }
    const bool mA = (amask[b*SSL + qt*128 + r0] == 0);
    const bool mB = (amask[b*SSL + qt*128 + r1] == 0);

    float tl0 = 0.0f, tl1 = 0.0f;
    float accO[8][4] = {};

    for (int it = 0; it < SSL/64; it++) {
        CP_WAIT0();
        __syncthreads();            // current buf fully resident + visible
        const int buf = it & 1;
        uint32_t* Ks = KsB + buf*KBUF;
        uint32_t* Vs = VsB + buf*VBUF;

        if (it + 1 < SSL/64) {      // prefetch next tile into buf^1 (free:
            uint32_t* Kn = KsB + (buf^1)*KBUF;   // all passed the barrier)
            uint32_t* Vn = VsB + (buf^1)*VBUF;
            size_t base = ((size_t)(b*SSL + (it+1)*64 + krow))*DD + h*HDD;
            #pragma unroll
            for (int j = 0; j < 4; j++) {
                int c = kv + 4*j;
                cpa16(&Kn[krow*AK_STR + 4*c], g_kt + base + 4*c);
                cpa16(&Vn[vprow*AV_STR + 4*c], g_v + base + 4*c);
            }
            CP_COMMIT();
        }

        // ---- S = (Q/8) @ K^T : warp computes 16x64 ----
        float accS[8][4] = {};
        #pragma unroll
        for (int ks = 0; ks < 8; ks++) {
            int kb = ks * 8;
            uint32_t a[4];
            a[0] = Qs[r0*AQ_STR + kb + lq];
            a[1] = Qs[r1*AQ_STR + kb + lq];
            a[2] = Qs[r0*AQ_STR + kb + 4 + lq];
            a[3] = Qs[r1*AQ_STR + kb + 4 + lq];
            #pragma unroll
            for (int nt = 0; nt < 8; nt++) {
                int key0 = 8*nt + lr;
                mma_tf32(accS[nt], a,
                         Ks[key0*AK_STR + kb + lq],
                         Ks[key0*AK_STR + kb + 4 + lq]);
            }
        }

        // ---- no-max softmax in registers: p = exp(s); masked rows p=1 ----
        #pragma unroll
        for (int nt = 0; nt < 8; nt++) {
            float p0 = mA ? 1.0f : __expf(accS[nt][0]);
            float p1 = mA ? 1.0f : __expf(accS[nt][1]);
            float p2 = mB ? 1.0f : __expf(accS[nt][2]);
            float p3 = mB ? 1.0f : __expf(accS[nt][3]);
            tl0 += p0 + p1;
            tl1 += p2 + p3;
            accS[nt][0] = p0; accS[nt][1] = p1;
            accS[nt][2] = p2; accS[nt][3] = p3;
        }

        // ---- O += P @ V' : P regs feed A directly (V rows permuted) ----
        #pragma unroll
        for (int nt = 0; nt < 8; nt++) {          // nt = key 8-block
            uint32_t a[4];
            a[0] = __float_as_uint(accS[nt][0]);  // P[r0][2lq]   -> slot lq
            a[1] = __float_as_uint(accS[nt][2]);  // P[r1][2lq]
            a[2] = __float_as_uint(accS[nt][1]);  // P[r0][2lq+1] -> slot lq+4
            a[3] = __float_as_uint(accS[nt][3]);  // P[r1][2lq+1]
            #pragma unroll
            for (int d = 0; d < 8; d++) {
                mma_tf32(accO[d], a,
                         Vs[(8*nt + lq)*AV_STR + 8*d + lr],
                         Vs[(8*nt + lq + 4)*AV_STR + 8*d + lr]);
            }
        }
    }

    // ---- epilogue: reduce l across quad, write O / l ----
    tl0 += __shfl_xor_sync(0xffffffffu, tl0, 1);
    tl0 += __shfl_xor_sync(0xffffffffu, tl0, 2);
    tl1 += __shfl_xor_sync(0xffffffffu, tl1, 1);
    tl1 += __shfl_xor_sync(0xffffffffu, tl1, 2);
    float li0 = 1.0f / tl0, li1 = 1.0f / tl1;
    size_t row0 = (size_t)(b*SSL + qt*128 + r0) * DD + h*HDD;
    size_t row1 = (size_t)(b*SSL + qt*128 + r1) * DD + h*HDD;
    #pragma unroll
    for (int d = 0; d < 8; d++) {
        int col = 8*d + 2*lq;
        *(float2*)(out + row0 + col) = make_float2(accO[d][0]*li0, accO[d][1]*li0);
        *(float2*)(out + row1 + col) = make_float2(accO[d][2]*li1, accO[d][3]*li1);
    }
}

// ---------------------------------------------------------------------------
extern "C" void kernel_launch(void* const* d_in, const int* in_sizes, int n_in,
                              void* d_out, int out_size)
{
    const float* X     = (const float*)d_in[0];
    const int*   amask = (const int*)  d_in[1];
    const float* Wq    = (const float*)d_in[2];
    const float* bq    = (const float*)d_in[3];
    const float* Wk    = (const float*)d_in[4];
    const float* bk    = (const float*)d_in[5];
    float*       out   = (float*)d_out;

    cudaFuncSetAttribute(proj_tc,
                         cudaFuncAttributeMaxDynamicSharedMemorySize, PROJ_SMEM);
    cudaFuncSetAttribute(attn_tc,
                         cudaFuncAttributeMaxDynamicSharedMemorySize, SMEM_ATTN);

    proj_tc<<<dim3(DD/64, MSZ/128), 256, PROJ_SMEM>>>(X, Wq, bq, Wk, bk);
    attn_tc<<<dim3(SSL/128, HH, BB), 256, SMEM_ATTN>>>(amask, out);
}

// round 12
// speedup vs baseline: 1.5871x; 1.0038x over previous
#include <cuda_runtime.h>
#include <math.h>
#include <stdint.h>

#define BB  2
#define SSL 2048
#define DD  1024
#define HH  16
#define HDD 64
#define MSZ (BB*SSL)

// Scratch (allocation-free rule: device globals). All tf32 bit patterns:
// g_q  = tf32(0.125*log2e * Q), dim-interleaved within 8-groups
//        (dim j -> position 2*(j&3)+(j>>2))
// g_kt = tf32(softplus(K)), dim-interleaved (same scheme)
// g_v  = tf32(Q + K), natural dim order
__device__ uint32_t g_q [MSZ*DD];
__device__ uint32_t g_kt[MSZ*DD];
__device__ uint32_t g_v [MSZ*DD];

// ---------------------------------------------------------------------------
// helpers
// ---------------------------------------------------------------------------
__device__ __forceinline__ uint32_t f2tf32(float x) {
    uint32_t r;
    asm("cvt.rna.tf32.f32 %0, %1;" : "=r"(r) : "f"(x));
    return r;
}

__device__ __forceinline__ float ex2f(float x) {
    float r;
    asm("ex2.approx.f32 %0, %1;" : "=f"(r) : "f"(x));
    return r;
}

__device__ __forceinline__ void mma_tf32(float c[4], const uint32_t a[4],
                                         uint32_t b0, uint32_t b1) {
    asm volatile(
        "mma.sync.aligned.m16n8k8.row.col.f32.tf32.tf32.f32 "
        "{%0,%1,%2,%3}, {%4,%5,%6,%7}, {%8,%9}, {%0,%1,%2,%3};"
        : "+f"(c[0]), "+f"(c[1]), "+f"(c[2]), "+f"(c[3])
        : "r"(a[0]), "r"(a[1]), "r"(a[2]), "r"(a[3]), "r"(b0), "r"(b1));
}

__device__ __forceinline__ float softplus_f(float x) {
    return (x > 15.0f) ? x : log1pf(__expf(x));
}

__device__ __forceinline__ void cpa16(void* s, const void* g) {
    uint32_t sa = (uint32_t)__cvta_generic_to_shared(s);
    asm volatile("cp.async.ca.shared.global [%0], [%1], 16;" :: "r"(sa), "l"(g));
}
#define CP_COMMIT() asm volatile("cp.async.commit_group;")
#define CP_WAIT0()  asm volatile("cp.async.wait_group 0;")

// Q scale: 1/sqrt(HD)=1/8 fused with log2(e) so softmax is a bare ex2.
#define QSCALE (0.125f * 1.44269504f)

// ---------------------------------------------------------------------------
// Fused projection (r6 body, known-good): Q and K on the same X tile.
// Epilogue writes tf32 bits: g_q (scaled, interleaved), g_kt (softplus,
// interleaved), g_v (natural). CTA 128m x 64n, k-tile 32, double-buffered.
// ---------------------------------------------------------------------------
#define XS_STR 36
#define WS_STR 72
#define XS_BUF (128*XS_STR)
#define WS_BUF (32*WS_STR)
#define PROJ_SMEM ((2*XS_BUF + 4*WS_BUF)*4)

__global__ void __launch_bounds__(256, 2) proj_tc(
    const float* __restrict__ X,
    const float* __restrict__ Wq, const float* __restrict__ bq,
    const float* __restrict__ Wk, const float* __restrict__ bk)
{
    extern __shared__ uint32_t psm[];
    uint32_t* XsB  = psm;
    uint32_t* WqsB = psm + 2*XS_BUF;
    uint32_t* WksB = WqsB + 2*WS_BUF;

    const int m0 = blockIdx.y * 128;
    const int n0 = blockIdx.x * 64;
    const int t    = threadIdx.x;
    const int warp = t >> 5;
    const int lane = t & 31;
    const int lq   = lane & 3;
    const int lr   = lane >> 2;
    const int wm = (warp >> 1) * 32;
    const int wn = (warp & 1) * 32;

    const int xr = t >> 1;
    const int xcb = (t & 1) * 4;
    const int wr = t >> 3;
    const int wcb = t & 7;

    float accq[2][4][4] = {};
    float acck[2][4][4] = {};

    {
        const float* xp = X + (size_t)(m0 + xr) * DD;
        #pragma unroll
        for (int j = 0; j < 4; j++) {
            int c = xcb + j;
            float4 f = *(const float4*)(xp + 4*c);
            *(uint4*)&XsB[xr*XS_STR + 4*c] =
                make_uint4(f2tf32(f.x), f2tf32(f.y), f2tf32(f.z), f2tf32(f.w));
        }
        const float* wqp = Wq + (size_t)wr * DD + n0;
        const float* wkp = Wk + (size_t)wr * DD + n0;
        #pragma unroll
        for (int j = 0; j < 2; j++) {
            int c = wcb + 8*j;
            float4 fq = *(const float4*)(wqp + 4*c);
            *(uint4*)&WqsB[wr*WS_STR + 4*c] =
                make_uint4(f2tf32(fq.x), f2tf32(fq.y), f2tf32(fq.z), f2tf32(fq.w));
            float4 fk = *(const float4*)(wkp + 4*c);
            *(uint4*)&WksB[wr*WS_STR + 4*c] =
                make_uint4(f2tf32(fk.x), f2tf32(fk.y), f2tf32(fk.z), f2tf32(fk.w));
        }
    }
    __syncthreads();

    for (int k0 = 0; k0 < DD; k0 += 32) {
        const int buf = (k0 >> 5) & 1;
        uint32_t* Xs  = XsB  + buf*XS_BUF;
        uint32_t* Wqs = WqsB + buf*WS_BUF;
        uint32_t* Wks = WksB + buf*WS_BUF;
        const bool more = (k0 + 32) < DD;

        float4 xst[4], wqst[2], wkst[2];
        if (more) {
            const float* xp = X + (size_t)(m0 + xr) * DD + k0 + 32;
            #pragma unroll
            for (int j = 0; j < 4; j++)
                xst[j] = *(const float4*)(xp + 4*(xcb + j));
            const float* wqp = Wq + (size_t)(k0 + 32 + wr) * DD + n0;
            const float* wkp = Wk + (size_t)(k0 + 32 + wr) * DD + n0;
            #pragma unroll
            for (int j = 0; j < 2; j++) {
                wqst[j] = *(const float4*)(wqp + 4*(wcb + 8*j));
                wkst[j] = *(const float4*)(wkp + 4*(wcb + 8*j));
            }
        }

        #pragma unroll
        for (int ks = 0; ks < 4; ks++) {
            int kb = ks * 8;
            uint32_t a[2][4];
            #pragma unroll
            for (int mt = 0; mt < 2; mt++) {
                int ar = wm + 16*mt + lr;
                a[mt][0] = Xs[ar*XS_STR + kb + lq];
                a[mt][1] = Xs[(ar+8)*XS_STR + kb + lq];
                a[mt][2] = Xs[ar*XS_STR + kb + lq + 4];
                a[mt][3] = Xs[(ar+8)*XS_STR + kb + lq + 4];
            }
            #pragma unroll
            for (int nt = 0; nt < 4; nt++) {
                int bc = wn + 8*nt + lr;
                uint32_t q0 = Wqs[(kb + lq)*WS_STR + bc];
                uint32_t q1 = Wqs[(kb + 4 + lq)*WS_STR + bc];
                uint32_t k0r = Wks[(kb + lq)*WS_STR + bc];
                uint32_t k1r = Wks[(kb + 4 + lq)*WS_STR + bc];
                #pragma unroll
                for (int mt = 0; mt < 2; mt++) {
                    mma_tf32(accq[mt][nt], a[mt], q0, q1);
                    mma_tf32(acck[mt][nt], a[mt], k0r, k1r);
                }
            }
        }

        if (more) {
            uint32_t* Xn  = XsB  + (buf^1)*XS_BUF;
            uint32_t* Wqn = WqsB + (buf^1)*WS_BUF;
            uint32_t* Wkn = WksB + (buf^1)*WS_BUF;
            #pragma unroll
            for (int j = 0; j < 4; j++) {
                float4 f = xst[j];
                *(uint4*)&Xn[xr*XS_STR + 4*(xcb + j)] =
                    make_uint4(f2tf32(f.x), f2tf32(f.y), f2tf32(f.z), f2tf32(f.w));
            }
            #pragma unroll
            for (int j = 0; j < 2; j++) {
                float4 fq = wqst[j];
                *(uint4*)&Wqn[wr*WS_STR + 4*(wcb + 8*j)] =
                    make_uint4(f2tf32(fq.x), f2tf32(fq.y), f2tf32(fq.z), f2tf32(fq.w));
                float4 fk = wkst[j];
                *(uint4*)&Wkn[wr*WS_STR + 4*(wcb + 8*j)] =
                    make_uint4(f2tf32(fk.x), f2tf32(fk.y), f2tf32(fk.z), f2tf32(fk.w));
            }
        }
        __syncthreads();
    }

    // epilogue: g_q/g_kt interleaved tf32 bits, g_v natural tf32 bits
    #pragma unroll
    for (int nt = 0; nt < 4; nt++) {
        int c = n0 + wn + 8*nt + 2*lq;
        float bqx = bq[c], bqy = bq[c+1];
        float bkx = bk[c], bky = bk[c+1];
        int cb = c & ~7, j = c & 7;
        int j0 = 2*(j&3) + (j>>2);
        int j1 = 2*((j+1)&3) + ((j+1)>>2);
        #pragma unroll
        for (int mt = 0; mt < 2; mt++) {
            #pragma unroll
            for (int half = 0; half < 2; half++) {
                int r = m0 + wm + 16*mt + lr + 8*half;
                float qx = accq[mt][nt][2*half+0] + bqx;
                float qy = accq[mt][nt][2*half+1] + bqy;
                float kx = acck[mt][nt][2*half+0] + bkx;
                float ky = acck[mt][nt][2*half+1] + bky;
                size_t off = (size_t)r * DD;
                g_q [off + cb + j0] = f2tf32(QSCALE*qx);
                g_q [off + cb + j1] = f2tf32(QSCALE*qy);
                g_kt[off + cb + j0] = f2tf32(softplus_f(kx));
                g_kt[off + cb + j1] = f2tf32(softplus_f(ky));
                *(uint2*)&g_v[off + c] = make_uint2(f2tf32(qx+kx), f2tf32(qy+ky));
            }
        }
    }
}

// ---------------------------------------------------------------------------
// Flash attention v7 (r11 base + LDS.64 frag loads + ex2 softmax):
// Q-tile 128, 256 threads (8 warps, warp tile 16x64), 2 CTAs/SM.
// Q/K dim-interleaved in global -> S-phase fragment loads are LDS.64
// (conflict-free at stride 72). P stays in registers (V rows permuted
// i -> i/2 + 4*(i&1) within 8-key groups; key-sum permutation-invariant).
// K/V double-buffered cp.async, wait at tile top. No-max softmax:
// p = 2^(s') with log2e folded into Q scale; masked query rows p = 1.
// ---------------------------------------------------------------------------
#define AQ_STR 72
#define AK_STR 72
#define AV_STR 72
#define KBUF (64*AK_STR)
#define VBUF (64*AV_STR)
#define SMEM_ATTN ((128*AQ_STR + 2*KBUF + 2*VBUF)*4)

__global__ void __launch_bounds__(256, 2) attn_tc(
    const int* __restrict__ amask, float* __restrict__ out)
{
    extern __shared__ uint32_t smu[];
    uint32_t* Qs  = smu;                  // [128][AQ_STR] interleaved dims
    uint32_t* KsB = Qs + 128*AQ_STR;      // [2][64][AK_STR] interleaved dims
    uint32_t* VsB = KsB + 2*KBUF;         // [2][64][AV_STR] natural, rows permuted

    const int qt = blockIdx.x, h = blockIdx.y, b = blockIdx.z;
    const int t    = threadIdx.x;
    const int warp = t >> 5;
    const int lane = t & 31;
    const int lq   = lane & 3;
    const int lr   = lane >> 2;
    const int r0 = warp*16 + lr, r1 = r0 + 8;
    const int qrow = t >> 1, qv = t & 1;   // Q loader: 128 rows x 2 threads
    const int krow = t >> 2, kv = t & 3;   // K/V loader: 64 rows x 4 chunks
    // permuted V row: within 8-group, key i -> row i/2 + 4*(i&1)
    const int vprow = (krow & ~7) + ((krow & 7) >> 1) + ((krow & 1) << 2);

    {   // Q tile + K/V tile 0, all async (verbatim row copies)
        const uint32_t* qg = g_q + ((size_t)(b*SSL + qt*128 + qrow))*DD + h*HDD;
        #pragma unroll
        for (int j = 0; j < 8; j++) {
            int c = 8*qv + j;
            cpa16(&Qs[qrow*AQ_STR + 4*c], qg + 4*c);
        }
        size_t base = ((size_t)(b*SSL + krow))*DD + h*HDD;
        #pragma unroll
        for (int j = 0; j < 4; j++) {
            int c = kv + 4*j;
            cpa16(&KsB[krow*AK_STR + 4*c], g_kt + base + 4*c);
            cpa16(&VsB[vprow*AV_STR + 4*c], g_v + base + 4*c);
        }
        CP_COMMIT();
    }
    const bool mA = (amask[b*SSL + qt*128 + r0] == 0);
    const bool mB = (amask[b*SSL + qt*128 + r1] == 0);

    float tl0 = 0.0f, tl1 = 0.0f;
    float accO[8][4] = {};

    for (int it = 0; it < SSL/64; it++) {
        CP_WAIT0();
        __syncthreads();            // current buf fully resident + visible
        const int buf = it & 1;
        uint32_t* Ks = KsB + buf*KBUF;
        uint32_t* Vs = VsB + buf*VBUF;

        if (it + 1 < SSL/64) {      // prefetch next tile into buf^1
            uint32_t* Kn = KsB + (buf^1)*KBUF;
            uint32_t* Vn = VsB + (buf^1)*VBUF;
            size_t base = ((size_t)(b*SSL + (it+1)*64 + krow))*DD + h*HDD;
            #pragma unroll
            for (int j = 0; j < 4; j++) {
                int c = kv + 4*j;
                cpa16(&Kn[krow*AK_STR + 4*c], g_kt + base + 4*c);
                cpa16(&Vn[vprow*AV_STR + 4*c], g_v + base + 4*c);
            }
            CP_COMMIT();
        }

        // ---- S' = (Q*qscale) @ K^T : warp computes 16x64, LDS.64 frags ----
        float accS[8][4] = {};
        #pragma unroll
        for (int ks = 0; ks < 8; ks++) {
            int kb = ks * 8;
            uint32_t a[4];
            uint2 u0 = *(const uint2*)&Qs[r0*AQ_STR + kb + 2*lq];
            uint2 u1 = *(const uint2*)&Qs[r1*AQ_STR + kb + 2*lq];
            a[0] = u0.x; a[1] = u1.x; a[2] = u0.y; a[3] = u1.y;
            #pragma unroll
            for (int nt = 0; nt < 8; nt++) {
                uint2 bb = *(const uint2*)&Ks[(8*nt + lr)*AK_STR + kb + 2*lq];
                mma_tf32(accS[nt], a, bb.x, bb.y);
            }
        }

        // ---- no-max softmax in registers: p = 2^(s'); masked rows p=1 ----
        #pragma unroll
        for (int nt = 0; nt < 8; nt++) {
            float p0 = mA ? 1.0f : ex2f(accS[nt][0]);
            float p1 = mA ? 1.0f : ex2f(accS[nt][1]);
            float p2 = mB ? 1.0f : ex2f(accS[nt][2]);
            float p3 = mB ? 1.0f : ex2f(accS[nt][3]);
            tl0 += p0 + p1;
            tl1 += p2 + p3;
            accS[nt][0] = p0; accS[nt][1] = p1;
            accS[nt][2] = p2; accS[nt][3] = p3;
        }

        // ---- O += P @ V' : P regs feed A directly (V rows permuted) ----
        #pragma unroll
        for (int nt = 0; nt < 8; nt++) {          // nt = key 8-block
            uint32_t a[4];
            a[0] = __float_as_uint(accS[nt][0]);  // P[r0][2lq]   -> slot lq
            a[1] = __float_as_uint(accS[nt][2]);  // P[r1][2lq]
            a[2] = __float_as_uint(accS[nt][1]);  // P[r0][2lq+1] -> slot lq+4
            a[3] = __float_as_uint(accS[nt][3]);  // P[r1][2lq+1]
            #pragma unroll
            for (int d = 0; d < 8; d++) {
                mma_tf32(accO[d], a,
                         Vs[(8*nt + lq)*AV_STR + 8*d + lr],
                         Vs[(8*nt + lq + 4)*AV_STR + 8*d + lr]);
            }
        }
    }

    // ---- epilogue: reduce l across quad, write O / l ----
    tl0 += __shfl_xor_sync(0xffffffffu, tl0, 1);
    tl0 += __shfl_xor_sync(0xffffffffu, tl0, 2);
    tl1 += __shfl_xor_sync(0xffffffffu, tl1, 1);
    tl1 += __shfl_xor_sync(0xffffffffu, tl1, 2);
    float li0 = 1.0f / tl0, li1 = 1.0f / tl1;
    size_t row0 = (size_t)(b*SSL + qt*128 + r0) * DD + h*HDD;
    size_t row1 = (size_t)(b*SSL + qt*128 + r1) * DD + h*HDD;
    #pragma unroll
    for (int d = 0; d < 8; d++) {
        int col = 8*d + 2*lq;
        *(float2*)(out + row0 + col) = make_float2(accO[d][0]*li0, accO[d][1]*li0);
        *(float2*)(out + row1 + col) = make_float2(accO[d][2]*li1, accO[d][3]*li1);
    }
}

// ---------------------------------------------------------------------------
extern "C" void kernel_launch(void* const* d_in, const int* in_sizes, int n_in,
                              void* d_out, int out_size)
{
    const float* X     = (const float*)d_in[0];
    const int*   amask = (const int*)  d_in[1];
    const float* Wq    = (const float*)d_in[2];
    const float* bq    = (const float*)d_in[3];
    const float* Wk    = (const float*)d_in[4];
    const float* bk    = (const float*)d_in[5];
    float*       out   = (float*)d_out;

    cudaFuncSetAttribute(proj_tc,
                         cudaFuncAttributeMaxDynamicSharedMemorySize, PROJ_SMEM);
    cudaFuncSetAttribute(attn_tc,
                         cudaFuncAttributeMaxDynamicSharedMemorySize, SMEM_ATTN);

    proj_tc<<<dim3(DD/64, MSZ/128), 256, PROJ_SMEM>>>(X, Wq, bq, Wk, bk);
    attn_tc<<<dim3(SSL/128, HH, BB), 256, SMEM_ATTN>>>(amask, out);
}